// round 7
// baseline (speedup 1.0000x reference)
#include <cuda_runtime.h>
#include <cstdint>

#define N_NODES 100000
#define N_EDGES 1600000
#define CH 64
#define EDIM 16
#define HID 32
#define NB_SCAN ((N_NODES + 1023) / 1024)   // 98

// Scratch (static device globals — allocation-free)
__device__ float g_xw[N_NODES * CH];              // x @ W
__device__ float g_alpha[N_EDGES];                // edge gate
__device__ float g_deg[N_NODES];                  // degree -> dis
__device__ int   g_cnt[N_NODES];
__device__ int   g_incl[N_NODES];
__device__ int   g_bsum[NB_SCAN];
__device__ int   g_boff[NB_SCAN];
__device__ int   g_rowptr[N_NODES];
__device__ int   g_wptr[N_NODES];
__device__ unsigned long long g_epack[N_EDGES];   // (norm<<32 | row) per CSR slot
__device__ int   g_is64;

// Edge-MLP weights in constant memory (uniform-const port, not LSU/L1)
__constant__ float c_W1[EDIM * HID];   // [k][j] row-major as given
__constant__ float c_b1[HID];
__constant__ float c_W2[HID];
__constant__ float c_b2[1];

// ---------------------------------------------------------------------------
// dtype detection (thread 0 of block 0) + zero deg/cnt
// ---------------------------------------------------------------------------
__global__ void k_detect_init(const long long* __restrict__ ei64) {
    int i = blockIdx.x * blockDim.x + threadIdx.x;
    if (i == 0) {
        int ok = 1;
        #pragma unroll 1
        for (int k = 0; k < 64; ++k) {
            long long v = ei64[k];
            if (v < 0 || v >= N_NODES) { ok = 0; break; }
        }
        g_is64 = ok;
    }
    if (i < N_NODES) { g_deg[i] = 0.0f; g_cnt[i] = 0; }
}

// ---------------------------------------------------------------------------
// 1) xw = x @ W   (independent of the edge chain -> side stream)
// ---------------------------------------------------------------------------
__global__ void k_xw(const float* __restrict__ x, const float* __restrict__ W) {
    __shared__ float Ws[CH * CH];
    for (int i = threadIdx.x; i < CH * CH; i += blockDim.x) Ws[i] = W[i];
    __syncthreads();
    const int c  = threadIdx.x & 63;
    const int ln = threadIdx.x >> 6;
    const int base = blockIdx.x * 64;
    for (int it = 0; it < 16; ++it) {
        int n = base + it * 4 + ln;
        if (n < N_NODES) {
            const float* xr = x + (size_t)n * CH;
            float acc = 0.0f;
            #pragma unroll
            for (int k = 0; k < CH; ++k) acc = fmaf(xr[k], Ws[k * CH + c], acc);
            g_xw[(size_t)n * CH + c] = acc;
        }
    }
}

// ---------------------------------------------------------------------------
// 2) edge MLP gate + degree + count.  Weights from __constant__ (LDCU path).
// ---------------------------------------------------------------------------
__global__ void k_edge(const float* __restrict__ ea,
                       const void* __restrict__ ei) {
    int e = blockIdx.x * blockDim.x + threadIdx.x;
    if (e >= N_EDGES) return;

    float4 a0, a1, a2, a3;
    {
        const float4* p = (const float4*)(ea + (size_t)e * EDIM);
        a0 = p[0]; a1 = p[1]; a2 = p[2]; a3 = p[3];
    }

    float acc = c_b2[0];
    #pragma unroll
    for (int j = 0; j < HID; ++j) {
        float h = c_b1[j];
        h = fmaf(a0.x, c_W1[ 0 * HID + j], h);
        h = fmaf(a0.y, c_W1[ 1 * HID + j], h);
        h = fmaf(a0.z, c_W1[ 2 * HID + j], h);
        h = fmaf(a0.w, c_W1[ 3 * HID + j], h);
        h = fmaf(a1.x, c_W1[ 4 * HID + j], h);
        h = fmaf(a1.y, c_W1[ 5 * HID + j], h);
        h = fmaf(a1.z, c_W1[ 6 * HID + j], h);
        h = fmaf(a1.w, c_W1[ 7 * HID + j], h);
        h = fmaf(a2.x, c_W1[ 8 * HID + j], h);
        h = fmaf(a2.y, c_W1[ 9 * HID + j], h);
        h = fmaf(a2.z, c_W1[10 * HID + j], h);
        h = fmaf(a2.w, c_W1[11 * HID + j], h);
        h = fmaf(a3.x, c_W1[12 * HID + j], h);
        h = fmaf(a3.y, c_W1[13 * HID + j], h);
        h = fmaf(a3.z, c_W1[14 * HID + j], h);
        h = fmaf(a3.w, c_W1[15 * HID + j], h);
        float s = __fdividef(h, 1.0f + __expf(-h));    // silu
        acc = fmaf(s, c_W2[j], acc);
    }
    float alpha = __fdividef(1.0f, 1.0f + __expf(-acc)); // sigmoid
    g_alpha[e] = alpha;

    int col;
    if (g_is64) col = (int)((const long long*)ei)[(size_t)N_EDGES + e];
    else        col = ((const int*)ei)[(size_t)N_EDGES + e];
    atomicAdd(&g_deg[col], alpha);
    atomicAdd(&g_cnt[col], 1);
}

// ---------------------------------------------------------------------------
// 3a) per-block inclusive scan of cnt
// ---------------------------------------------------------------------------
__global__ void k_scan1() {
    int i = blockIdx.x * 1024 + threadIdx.x;
    int v = (i < N_NODES) ? g_cnt[i] : 0;
    int lane = threadIdx.x & 31, wid = threadIdx.x >> 5;
    int s = v;
    #pragma unroll
    for (int o = 1; o < 32; o <<= 1) {
        int t = __shfl_up_sync(0xffffffffu, s, o);
        if (lane >= o) s += t;
    }
    __shared__ int wsum[32];
    if (lane == 31) wsum[wid] = s;
    __syncthreads();
    if (wid == 0) {
        int t = wsum[lane];
        #pragma unroll
        for (int o = 1; o < 32; o <<= 1) {
            int u = __shfl_up_sync(0xffffffffu, t, o);
            if (lane >= o) t += u;
        }
        wsum[lane] = t;
    }
    __syncthreads();
    int incl = s + (wid > 0 ? wsum[wid - 1] : 0);
    if (i < N_NODES) g_incl[i] = incl;
    if (threadIdx.x == 1023) g_bsum[blockIdx.x] = incl;
}

// ---------------------------------------------------------------------------
// 3b) scan the 98 block sums with ONE warp (4 contiguous elems per lane)
// ---------------------------------------------------------------------------
__global__ void k_scan2() {
    int lane = threadIdx.x;              // launched with 32 threads
    int base = lane * 4;
    int v0 = 0, v1 = 0, v2 = 0, v3 = 0;
    if (base + 0 < NB_SCAN) v0 = g_bsum[base + 0];
    if (base + 1 < NB_SCAN) v1 = g_bsum[base + 1];
    if (base + 2 < NB_SCAN) v2 = g_bsum[base + 2];
    if (base + 3 < NB_SCAN) v3 = g_bsum[base + 3];
    int local = v0 + v1 + v2 + v3;
    int run = local;
    #pragma unroll
    for (int o = 1; o < 32; o <<= 1) {
        int t = __shfl_up_sync(0xffffffffu, run, o);
        if (lane >= o) run += t;
    }
    int acc = run - local;               // exclusive prefix of this lane's chunk
    if (base + 0 < NB_SCAN) g_boff[base + 0] = acc;  acc += v0;
    if (base + 1 < NB_SCAN) g_boff[base + 1] = acc;  acc += v1;
    if (base + 2 < NB_SCAN) g_boff[base + 2] = acc;  acc += v2;
    if (base + 3 < NB_SCAN) g_boff[base + 3] = acc;
}

// ---------------------------------------------------------------------------
// 3c) finalize rowptr/wptr + dis = rsqrt(deg)
// ---------------------------------------------------------------------------
__global__ void k_final() {
    int i = blockIdx.x * blockDim.x + threadIdx.x;
    if (i < N_NODES) {
        int excl = g_incl[i] - g_cnt[i] + g_boff[i >> 10];
        g_rowptr[i] = excl;
        g_wptr[i] = excl;
        float d = g_deg[i];
        g_deg[i] = (d > 0.0f) ? rsqrtf(d) : 0.0f;
    }
}

// ---------------------------------------------------------------------------
// 4) placement: drop packed (row, norm) into col's CSR slot (one STG.64)
// ---------------------------------------------------------------------------
__global__ void k_place(const void* __restrict__ ei) {
    int e = blockIdx.x * blockDim.x + threadIdx.x;
    if (e >= N_EDGES) return;
    int row, col;
    if (g_is64) {
        row = (int)((const long long*)ei)[e];
        col = (int)((const long long*)ei)[(size_t)N_EDGES + e];
    } else {
        row = ((const int*)ei)[e];
        col = ((const int*)ei)[(size_t)N_EDGES + e];
    }
    float norm = g_deg[row] * g_alpha[e] * g_deg[col];
    int pos = atomicAdd(&g_wptr[col], 1);
    unsigned long long v = (unsigned)row |
                           ((unsigned long long)__float_as_uint(norm) << 32);
    g_epack[pos] = v;
}

// ---------------------------------------------------------------------------
// 5) gather + bias + LayerNorm + SiLU + residual.  One warp per node, MLP=8.
// ---------------------------------------------------------------------------
__global__ void k_gather_ln(const float* __restrict__ x, const float* __restrict__ b,
                            const float* __restrict__ gamma, const float* __restrict__ beta,
                            float* __restrict__ out) {
    __shared__ unsigned long long stage[8][40];   // 32 + 8 pad (zeros for tail)
    int wip  = threadIdx.x >> 5;
    int lane = threadIdx.x & 31;
    int node = (blockIdx.x * blockDim.x + threadIdx.x) >> 5;
    if (node >= N_NODES) return;

    if (lane < 8) stage[wip][32 + lane] = 0ull;

    int start = g_rowptr[node];
    int cnt   = g_cnt[node];

    float ax[8], ay[8];
    #pragma unroll
    for (int i = 0; i < 8; ++i) { ax[i] = 0.f; ay[i] = 0.f; }

    for (int base = 0; base < cnt; base += 32) {
        int m = cnt - base; if (m > 32) m = 32;
        unsigned long long p = 0ull;
        if (lane < m) p = g_epack[start + base + lane];
        stage[wip][lane] = p;
        __syncwarp();
        int m8 = (m + 7) & ~7;
        #pragma unroll 1
        for (int j = 0; j < m8; j += 8) {
            int   r[8]; float w[8];
            #pragma unroll
            for (int q = 0; q < 8; ++q) {
                unsigned long long pq = stage[wip][j + q];
                r[q] = (int)(unsigned)pq;
                w[q] = __uint_as_float((unsigned)(pq >> 32));
            }
            float2 v[8];
            #pragma unroll
            for (int q = 0; q < 8; ++q)
                v[q] = ((const float2*)(g_xw + (size_t)r[q] * CH))[lane];
            #pragma unroll
            for (int q = 0; q < 8; ++q) {
                ax[q] = fmaf(v[q].x, w[q], ax[q]);
                ay[q] = fmaf(v[q].y, w[q], ay[q]);
            }
        }
        __syncwarp();
    }

    float2 bb = ((const float2*)b)[lane];
    float h0 = ((ax[0] + ax[1]) + (ax[2] + ax[3])) + ((ax[4] + ax[5]) + (ax[6] + ax[7])) + bb.x;
    float h1 = ((ay[0] + ay[1]) + (ay[2] + ay[3])) + ((ay[4] + ay[5]) + (ay[6] + ay[7])) + bb.y;

    float s = h0 + h1;
    #pragma unroll
    for (int o = 16; o > 0; o >>= 1) s += __shfl_xor_sync(0xffffffffu, s, o);
    float mu = s * (1.0f / 64.0f);
    float d0 = h0 - mu, d1 = h1 - mu;
    float vs = d0 * d0 + d1 * d1;
    #pragma unroll
    for (int o = 16; o > 0; o >>= 1) vs += __shfl_xor_sync(0xffffffffu, vs, o);
    float inv = rsqrtf(vs * (1.0f / 64.0f) + 1e-5f);

    float2 gg = ((const float2*)gamma)[lane];
    float2 be = ((const float2*)beta)[lane];
    float y0 = fmaf(d0 * inv, gg.x, be.x);
    float y1 = fmaf(d1 * inv, gg.y, be.y);
    y0 = __fdividef(y0, 1.0f + __expf(-y0));
    y1 = __fdividef(y1, 1.0f + __expf(-y1));

    float2 xv = ((const float2*)(x + (size_t)node * CH))[lane];
    ((float2*)(out + (size_t)node * CH))[lane] = make_float2(y0 + xv.x, y1 + xv.y);
}

// ---------------------------------------------------------------------------
extern "C" void kernel_launch(void* const* d_in, const int* in_sizes, int n_in,
                              void* d_out, int out_size) {
    const float* x     = (const float*)d_in[0];
    const void*  ei    = d_in[1];
    const float* ea    = (const float*)d_in[2];
    const float* W     = (const float*)d_in[3];
    const float* b     = (const float*)d_in[4];
    const float* W1    = (const float*)d_in[5];
    const float* b1    = (const float*)d_in[6];
    const float* W2    = (const float*)d_in[7];
    const float* b2    = (const float*)d_in[8];
    const float* gamma = (const float*)d_in[9];
    const float* beta  = (const float*)d_in[10];
    float* out = (float*)d_out;

    static cudaStream_t s_side = nullptr;
    static cudaEvent_t  s_evFork = nullptr, s_evJoin = nullptr;
    static void *s_cW1 = nullptr, *s_cb1 = nullptr, *s_cW2 = nullptr, *s_cb2 = nullptr;
    if (!s_side) {
        cudaStreamCreateWithFlags(&s_side, cudaStreamNonBlocking);
        cudaEventCreateWithFlags(&s_evFork, cudaEventDisableTiming);
        cudaEventCreateWithFlags(&s_evJoin, cudaEventDisableTiming);
        cudaGetSymbolAddress(&s_cW1, c_W1);
        cudaGetSymbolAddress(&s_cb1, c_b1);
        cudaGetSymbolAddress(&s_cW2, c_W2);
        cudaGetSymbolAddress(&s_cb2, c_b2);
    }

    // stage edge-MLP weights into constant bank (D2D memcpy nodes)
    cudaMemcpyAsync(s_cW1, W1, EDIM * HID * sizeof(float), cudaMemcpyDeviceToDevice, 0);
    cudaMemcpyAsync(s_cb1, b1, HID * sizeof(float),        cudaMemcpyDeviceToDevice, 0);
    cudaMemcpyAsync(s_cW2, W2, HID * sizeof(float),        cudaMemcpyDeviceToDevice, 0);
    cudaMemcpyAsync(s_cb2, b2, sizeof(float),              cudaMemcpyDeviceToDevice, 0);

    // fork: xw on side stream, hidden under the edge chain
    cudaEventRecord(s_evFork, 0);
    cudaStreamWaitEvent(s_side, s_evFork, 0);
    k_xw<<<(N_NODES + 63) / 64, 256, 0, s_side>>>(x, W);
    cudaEventRecord(s_evJoin, s_side);

    // main chain
    k_detect_init<<<(N_NODES + 255) / 256, 256>>>((const long long*)ei);
    k_edge<<<(N_EDGES + 255) / 256, 256>>>(ea, ei);
    k_scan1<<<NB_SCAN, 1024>>>();
    k_scan2<<<1, 32>>>();
    k_final<<<(N_NODES + 255) / 256, 256>>>();
    k_place<<<(N_EDGES + 255) / 256, 256>>>(ei);

    // join: gather needs g_xw
    cudaStreamWaitEvent(0, s_evJoin, 0);
    k_gather_ln<<<(N_NODES + 7) / 8, 256>>>(x, b, gamma, beta, out);
}

// round 9
// speedup vs baseline: 1.0455x; 1.0455x over previous
#include <cuda_runtime.h>
#include <cstdint>

#define N_NODES 100000
#define N_EDGES 1600000
#define CH 64
#define EDIM 16
#define HID 32
#define NB_SCAN ((N_NODES + 1023) / 1024)   // 98

// Scratch (static device globals — allocation-free)
__device__ float g_xw[N_NODES * CH];              // x @ W
__device__ float g_alpha[N_EDGES];                // edge gate
__device__ float g_deg[N_NODES];                  // degree -> dis
__device__ int   g_cnt[N_NODES];
__device__ int   g_rowptr[N_NODES];
__device__ int   g_wptr[N_NODES];
__device__ unsigned long long g_epack[N_EDGES];   // (norm<<32 | row) per CSR slot
__device__ int   g_is64;
__device__ int   g_base;                          // ticket counter for block offsets

// ---------------------------------------------------------------------------
// dtype detection (one warp, parallel) + zero deg/cnt + zero ticket
// ---------------------------------------------------------------------------
__global__ void k_detect_init(const long long* __restrict__ ei64) {
    int i = blockIdx.x * blockDim.x + threadIdx.x;
    if (blockIdx.x == 0 && threadIdx.x < 32) {
        long long v0 = ei64[threadIdx.x];
        long long v1 = ei64[threadIdx.x + 32];
        int ok = (v0 >= 0 && v0 < N_NODES && v1 >= 0 && v1 < N_NODES) ? 1 : 0;
        unsigned m = __ballot_sync(0xffffffffu, ok);
        if (threadIdx.x == 0) { g_is64 = (m == 0xffffffffu); g_base = 0; }
    }
    if (i < N_NODES) { g_deg[i] = 0.0f; g_cnt[i] = 0; }
}

// ---------------------------------------------------------------------------
// 1) xw = x @ W   (side stream; overlaps the edge chain)
// ---------------------------------------------------------------------------
__global__ void k_xw(const float* __restrict__ x, const float* __restrict__ W) {
    __shared__ float Ws[CH * CH];
    for (int i = threadIdx.x; i < CH * CH; i += blockDim.x) Ws[i] = W[i];
    __syncthreads();
    const int c  = threadIdx.x & 63;
    const int ln = threadIdx.x >> 6;
    const int base = blockIdx.x * 64;
    for (int it = 0; it < 16; ++it) {
        int n = base + it * 4 + ln;
        if (n < N_NODES) {
            const float* xr = x + (size_t)n * CH;
            float acc = 0.0f;
            #pragma unroll
            for (int k = 0; k < CH; ++k) acc = fmaf(xr[k], Ws[k * CH + c], acc);
            g_xw[(size_t)n * CH + c] = acc;
        }
    }
}

// ---------------------------------------------------------------------------
// 2) edge MLP gate + degree + count.  W1 transposed in smem -> LDS.128.
// ---------------------------------------------------------------------------
__global__ void k_edge(const float* __restrict__ ea,
                       const void* __restrict__ ei,
                       const float* __restrict__ W1, const float* __restrict__ b1,
                       const float* __restrict__ W2, const float* __restrict__ b2) {
    __shared__ __align__(16) float sW1t[HID * EDIM];   // [j][k] transposed
    __shared__ float sb1[HID];
    __shared__ float sW2[HID];
    __shared__ float sb2;
    for (int i = threadIdx.x; i < HID * EDIM; i += blockDim.x) {
        int j = i >> 4, k = i & 15;
        sW1t[i] = W1[k * HID + j];
    }
    if (threadIdx.x < HID) { sb1[threadIdx.x] = b1[threadIdx.x]; sW2[threadIdx.x] = W2[threadIdx.x]; }
    if (threadIdx.x == 0) sb2 = b2[0];
    __syncthreads();

    int e = blockIdx.x * blockDim.x + threadIdx.x;
    if (e >= N_EDGES) return;

    float4 a0, a1, a2, a3;
    {
        const float4* p = (const float4*)(ea + (size_t)e * EDIM);
        a0 = p[0]; a1 = p[1]; a2 = p[2]; a3 = p[3];
    }

    const float4* Wt = (const float4*)sW1t;
    float acc = sb2;
    #pragma unroll
    for (int j = 0; j < HID; ++j) {
        float4 w0 = Wt[j * 4 + 0], w1 = Wt[j * 4 + 1], w2 = Wt[j * 4 + 2], w3 = Wt[j * 4 + 3];
        float h = sb1[j];
        h = fmaf(a0.x, w0.x, h); h = fmaf(a0.y, w0.y, h); h = fmaf(a0.z, w0.z, h); h = fmaf(a0.w, w0.w, h);
        h = fmaf(a1.x, w1.x, h); h = fmaf(a1.y, w1.y, h); h = fmaf(a1.z, w1.z, h); h = fmaf(a1.w, w1.w, h);
        h = fmaf(a2.x, w2.x, h); h = fmaf(a2.y, w2.y, h); h = fmaf(a2.z, w2.z, h); h = fmaf(a2.w, w2.w, h);
        h = fmaf(a3.x, w3.x, h); h = fmaf(a3.y, w3.y, h); h = fmaf(a3.z, w3.z, h); h = fmaf(a3.w, w3.w, h);
        float s = __fdividef(h, 1.0f + __expf(-h));    // silu
        acc = fmaf(s, sW2[j], acc);
    }
    float alpha = __fdividef(1.0f, 1.0f + __expf(-acc)); // sigmoid
    g_alpha[e] = alpha;

    int col;
    if (g_is64) col = (int)((const long long*)ei)[(size_t)N_EDGES + e];
    else        col = ((const int*)ei)[(size_t)N_EDGES + e];
    atomicAdd(&g_deg[col], alpha);
    atomicAdd(&g_cnt[col], 1);
}

// ---------------------------------------------------------------------------
// 3) single-pass scan: block-local inclusive scan + atomic ticket for the
//    block offset (offsets partition [0,E); order irrelevant for correctness),
//    then rowptr/wptr directly + dis = rsqrt(deg).
// ---------------------------------------------------------------------------
__global__ void k_scan() {
    int i = blockIdx.x * 1024 + threadIdx.x;
    int v = (i < N_NODES) ? g_cnt[i] : 0;
    int lane = threadIdx.x & 31, wid = threadIdx.x >> 5;
    int s = v;
    #pragma unroll
    for (int o = 1; o < 32; o <<= 1) {
        int t = __shfl_up_sync(0xffffffffu, s, o);
        if (lane >= o) s += t;
    }
    __shared__ int wsum[32];
    __shared__ int blkoff;
    if (lane == 31) wsum[wid] = s;
    __syncthreads();
    if (wid == 0) {
        int t = wsum[lane];
        #pragma unroll
        for (int o = 1; o < 32; o <<= 1) {
            int u = __shfl_up_sync(0xffffffffu, t, o);
            if (lane >= o) t += u;
        }
        wsum[lane] = t;
        if (lane == 31) blkoff = atomicAdd(&g_base, t);  // t = block total
    }
    __syncthreads();
    if (i < N_NODES) {
        int incl = s + (wid > 0 ? wsum[wid - 1] : 0);
        int excl = incl - v + blkoff;
        g_rowptr[i] = excl;
        g_wptr[i]   = excl;
        float d = g_deg[i];
        g_deg[i] = (d > 0.0f) ? rsqrtf(d) : 0.0f;
    }
}

// ---------------------------------------------------------------------------
// 4) placement: drop packed (row, norm) into col's CSR slot (one STG.64)
// ---------------------------------------------------------------------------
__global__ void k_place(const void* __restrict__ ei) {
    int e = blockIdx.x * blockDim.x + threadIdx.x;
    if (e >= N_EDGES) return;
    int row, col;
    if (g_is64) {
        row = (int)((const long long*)ei)[e];
        col = (int)((const long long*)ei)[(size_t)N_EDGES + e];
    } else {
        row = ((const int*)ei)[e];
        col = ((const int*)ei)[(size_t)N_EDGES + e];
    }
    float norm = g_deg[row] * g_alpha[e] * g_deg[col];
    int pos = atomicAdd(&g_wptr[col], 1);
    unsigned long long v = (unsigned)row |
                           ((unsigned long long)__float_as_uint(norm) << 32);
    g_epack[pos] = v;
}

// ---------------------------------------------------------------------------
// 5) gather + bias + LayerNorm + SiLU + residual.  One warp per node, MLP=8.
// ---------------------------------------------------------------------------
__global__ void k_gather_ln(const float* __restrict__ x, const float* __restrict__ b,
                            const float* __restrict__ gamma, const float* __restrict__ beta,
                            float* __restrict__ out) {
    __shared__ unsigned long long stage[8][40];   // 32 + 8 pad (zeros for tail)
    int wip  = threadIdx.x >> 5;
    int lane = threadIdx.x & 31;
    int node = (blockIdx.x * blockDim.x + threadIdx.x) >> 5;
    if (node >= N_NODES) return;

    if (lane < 8) stage[wip][32 + lane] = 0ull;

    int start = g_rowptr[node];
    int cnt   = g_cnt[node];

    float ax[8], ay[8];
    #pragma unroll
    for (int i = 0; i < 8; ++i) { ax[i] = 0.f; ay[i] = 0.f; }

    for (int base = 0; base < cnt; base += 32) {
        int m = cnt - base; if (m > 32) m = 32;
        unsigned long long p = 0ull;
        if (lane < m) p = g_epack[start + base + lane];
        stage[wip][lane] = p;
        __syncwarp();
        int m8 = (m + 7) & ~7;
        #pragma unroll 1
        for (int j = 0; j < m8; j += 8) {
            int   r[8]; float w[8];
            #pragma unroll
            for (int q = 0; q < 8; ++q) {
                unsigned long long pq = stage[wip][j + q];
                r[q] = (int)(unsigned)pq;
                w[q] = __uint_as_float((unsigned)(pq >> 32));
            }
            float2 v[8];
            #pragma unroll
            for (int q = 0; q < 8; ++q)
                v[q] = ((const float2*)(g_xw + (size_t)r[q] * CH))[lane];
            #pragma unroll
            for (int q = 0; q < 8; ++q) {
                ax[q] = fmaf(v[q].x, w[q], ax[q]);
                ay[q] = fmaf(v[q].y, w[q], ay[q]);
            }
        }
        __syncwarp();
    }

    float2 bb = ((const float2*)b)[lane];
    float h0 = ((ax[0] + ax[1]) + (ax[2] + ax[3])) + ((ax[4] + ax[5]) + (ax[6] + ax[7])) + bb.x;
    float h1 = ((ay[0] + ay[1]) + (ay[2] + ay[3])) + ((ay[4] + ay[5]) + (ay[6] + ay[7])) + bb.y;

    float s = h0 + h1;
    #pragma unroll
    for (int o = 16; o > 0; o >>= 1) s += __shfl_xor_sync(0xffffffffu, s, o);
    float mu = s * (1.0f / 64.0f);
    float d0 = h0 - mu, d1 = h1 - mu;
    float vs = d0 * d0 + d1 * d1;
    #pragma unroll
    for (int o = 16; o > 0; o >>= 1) vs += __shfl_xor_sync(0xffffffffu, vs, o);
    float inv = rsqrtf(vs * (1.0f / 64.0f) + 1e-5f);

    float2 gg = ((const float2*)gamma)[lane];
    float2 be = ((const float2*)beta)[lane];
    float y0 = fmaf(d0 * inv, gg.x, be.x);
    float y1 = fmaf(d1 * inv, gg.y, be.y);
    y0 = __fdividef(y0, 1.0f + __expf(-y0));
    y1 = __fdividef(y1, 1.0f + __expf(-y1));

    float2 xv = ((const float2*)(x + (size_t)node * CH))[lane];
    ((float2*)(out + (size_t)node * CH))[lane] = make_float2(y0 + xv.x, y1 + xv.y);
}

// ---------------------------------------------------------------------------
extern "C" void kernel_launch(void* const* d_in, const int* in_sizes, int n_in,
                              void* d_out, int out_size) {
    const float* x     = (const float*)d_in[0];
    const void*  ei    = d_in[1];
    const float* ea    = (const float*)d_in[2];
    const float* W     = (const float*)d_in[3];
    const float* b     = (const float*)d_in[4];
    const float* W1    = (const float*)d_in[5];
    const float* b1    = (const float*)d_in[6];
    const float* W2    = (const float*)d_in[7];
    const float* b2    = (const float*)d_in[8];
    const float* gamma = (const float*)d_in[9];
    const float* beta  = (const float*)d_in[10];
    float* out = (float*)d_out;

    static cudaStream_t s_side = nullptr;
    static cudaEvent_t  s_evFork = nullptr, s_evJoin = nullptr;
    if (!s_side) {
        cudaStreamCreateWithFlags(&s_side, cudaStreamNonBlocking);
        cudaEventCreateWithFlags(&s_evFork, cudaEventDisableTiming);
        cudaEventCreateWithFlags(&s_evJoin, cudaEventDisableTiming);
    }

    // (1) init + detect
    k_detect_init<<<(N_NODES + 255) / 256, 256>>>((const long long*)ei);

    // fork: xw on side stream; overlaps edge/scan/place on the main stream
    cudaEventRecord(s_evFork, 0);
    cudaStreamWaitEvent(s_side, s_evFork, 0);
    k_xw<<<(N_NODES + 63) / 64, 256, 0, s_side>>>(x, W);
    cudaEventRecord(s_evJoin, s_side);

    // main chain; k_place is the 4th kernel launch -> profiled next round
    k_edge<<<(N_EDGES + 255) / 256, 256>>>(ea, ei, W1, b1, W2, b2);
    k_scan<<<NB_SCAN, 1024>>>();
    k_place<<<(N_EDGES + 255) / 256, 256>>>(ei);

    // join: gather needs g_xw + CSR
    cudaStreamWaitEvent(0, s_evJoin, 0);
    k_gather_ln<<<(N_NODES + 7) / 8, 256>>>(x, b, gamma, beta, out);
}

// round 10
// speedup vs baseline: 1.1033x; 1.0553x over previous
#include <cuda_runtime.h>
#include <cstdint>

#define N_NODES 100000
#define N_EDGES 1600000
#define CH 64
#define EDIM 16
#define HID 32
#define NB_SCAN ((N_NODES + 1023) / 1024)   // 98

// Scratch (static device globals — allocation-free)
__device__ float g_xw[N_NODES * CH];              // x @ W
__device__ float g_alpha[N_EDGES];                // edge gate
__device__ float g_deg[N_NODES];                  // degree -> dis
__device__ int   g_cnt[N_NODES];
__device__ int   g_rowptr[N_NODES];
__device__ int   g_wptr[N_NODES];
__device__ unsigned long long g_epack[N_EDGES];   // (norm<<32 | row) per CSR slot
__device__ int   g_is64;
__device__ int   g_base;                          // ticket counter for block offsets

// ---------------------------------------------------------------------------
// dtype detection (one warp, parallel) + zero deg/cnt + zero ticket
// ---------------------------------------------------------------------------
__global__ void k_detect_init(const long long* __restrict__ ei64) {
    int i = blockIdx.x * blockDim.x + threadIdx.x;
    if (blockIdx.x == 0 && threadIdx.x < 32) {
        long long v0 = ei64[threadIdx.x];
        long long v1 = ei64[threadIdx.x + 32];
        int ok = (v0 >= 0 && v0 < N_NODES && v1 >= 0 && v1 < N_NODES) ? 1 : 0;
        unsigned m = __ballot_sync(0xffffffffu, ok);
        if (threadIdx.x == 0) { g_is64 = (m == 0xffffffffu); g_base = 0; }
    }
    if (i < N_NODES) { g_deg[i] = 0.0f; g_cnt[i] = 0; }
}

// ---------------------------------------------------------------------------
// 1) xw = x @ W   (side stream; overlaps the edge chain)
// ---------------------------------------------------------------------------
__global__ void k_xw(const float* __restrict__ x, const float* __restrict__ W) {
    __shared__ float Ws[CH * CH];
    for (int i = threadIdx.x; i < CH * CH; i += blockDim.x) Ws[i] = W[i];
    __syncthreads();
    const int c  = threadIdx.x & 63;
    const int ln = threadIdx.x >> 6;
    const int base = blockIdx.x * 64;
    for (int it = 0; it < 16; ++it) {
        int n = base + it * 4 + ln;
        if (n < N_NODES) {
            const float* xr = x + (size_t)n * CH;
            float acc = 0.0f;
            #pragma unroll
            for (int k = 0; k < CH; ++k) acc = fmaf(xr[k], Ws[k * CH + c], acc);
            g_xw[(size_t)n * CH + c] = acc;
        }
    }
}

// ---------------------------------------------------------------------------
// 2) edge MLP gate + degree + count.  TWO edges per thread, scalar fp32:
//    each warp-uniform weight LDS.128 feeds both edges (halves weight-LDS
//    per edge); FMA chains have ILP=2 across the edge pair.
// ---------------------------------------------------------------------------
__global__ void k_edge(const float* __restrict__ ea,
                       const void* __restrict__ ei,
                       const float* __restrict__ W1, const float* __restrict__ b1,
                       const float* __restrict__ W2, const float* __restrict__ b2) {
    __shared__ __align__(16) float sW1t[HID * EDIM];   // [j][k] transposed
    __shared__ float sb1[HID];
    __shared__ float sW2[HID];
    __shared__ float sb2;
    for (int i = threadIdx.x; i < HID * EDIM; i += blockDim.x) {
        int j = i >> 4, k = i & 15;
        sW1t[i] = W1[k * HID + j];
    }
    if (threadIdx.x < HID) { sb1[threadIdx.x] = b1[threadIdx.x]; sW2[threadIdx.x] = W2[threadIdx.x]; }
    if (threadIdx.x == 0) sb2 = b2[0];
    __syncthreads();

    int t  = blockIdx.x * blockDim.x + threadIdx.x;
    int e0 = 2 * t;
    if (e0 >= N_EDGES) return;      // N_EDGES even -> e0+1 also valid

    float4 A0[4], A1[4];
    {
        const float4* p0 = (const float4*)(ea + (size_t)e0 * EDIM);
        const float4* p1 = (const float4*)(ea + (size_t)(e0 + 1) * EDIM);
        #pragma unroll
        for (int i = 0; i < 4; ++i) { A0[i] = p0[i]; A1[i] = p1[i]; }
    }

    const float4* Wt = (const float4*)sW1t;
    float acc0 = sb2, acc1 = sb2;
    #pragma unroll
    for (int j = 0; j < HID; ++j) {
        float bj = sb1[j];
        float h0 = bj, h1 = bj;
        #pragma unroll
        for (int q = 0; q < 4; ++q) {
            float4 w = Wt[j * 4 + q];
            float4 a = A0[q], c = A1[q];
            h0 = fmaf(a.x, w.x, h0);  h1 = fmaf(c.x, w.x, h1);
            h0 = fmaf(a.y, w.y, h0);  h1 = fmaf(c.y, w.y, h1);
            h0 = fmaf(a.z, w.z, h0);  h1 = fmaf(c.z, w.z, h1);
            h0 = fmaf(a.w, w.w, h0);  h1 = fmaf(c.w, w.w, h1);
        }
        float w2 = sW2[j];
        float s0 = __fdividef(h0, 1.0f + __expf(-h0));   // silu
        float s1 = __fdividef(h1, 1.0f + __expf(-h1));
        acc0 = fmaf(s0, w2, acc0);
        acc1 = fmaf(s1, w2, acc1);
    }
    float alpha0 = __fdividef(1.0f, 1.0f + __expf(-acc0)); // sigmoid
    float alpha1 = __fdividef(1.0f, 1.0f + __expf(-acc1));
    ((float2*)g_alpha)[t] = make_float2(alpha0, alpha1);

    int col0, col1;
    if (g_is64) {
        col0 = (int)((const long long*)ei)[(size_t)N_EDGES + e0];
        col1 = (int)((const long long*)ei)[(size_t)N_EDGES + e0 + 1];
    } else {
        col0 = ((const int*)ei)[(size_t)N_EDGES + e0];
        col1 = ((const int*)ei)[(size_t)N_EDGES + e0 + 1];
    }
    atomicAdd(&g_deg[col0], alpha0);
    atomicAdd(&g_cnt[col0], 1);
    atomicAdd(&g_deg[col1], alpha1);
    atomicAdd(&g_cnt[col1], 1);
}

// ---------------------------------------------------------------------------
// 3) single-pass scan: block-local inclusive scan + atomic ticket offsets,
//    rowptr/wptr + dis = rsqrt(deg) inline.
// ---------------------------------------------------------------------------
__global__ void k_scan() {
    int i = blockIdx.x * 1024 + threadIdx.x;
    int v = (i < N_NODES) ? g_cnt[i] : 0;
    int lane = threadIdx.x & 31, wid = threadIdx.x >> 5;
    int s = v;
    #pragma unroll
    for (int o = 1; o < 32; o <<= 1) {
        int t = __shfl_up_sync(0xffffffffu, s, o);
        if (lane >= o) s += t;
    }
    __shared__ int wsum[32];
    __shared__ int blkoff;
    if (lane == 31) wsum[wid] = s;
    __syncthreads();
    if (wid == 0) {
        int t = wsum[lane];
        #pragma unroll
        for (int o = 1; o < 32; o <<= 1) {
            int u = __shfl_up_sync(0xffffffffu, t, o);
            if (lane >= o) t += u;
        }
        wsum[lane] = t;
        if (lane == 31) blkoff = atomicAdd(&g_base, t);  // t = block total
    }
    __syncthreads();
    if (i < N_NODES) {
        int incl = s + (wid > 0 ? wsum[wid - 1] : 0);
        int excl = incl - v + blkoff;
        g_rowptr[i] = excl;
        g_wptr[i]   = excl;
        float d = g_deg[i];
        g_deg[i] = (d > 0.0f) ? rsqrtf(d) : 0.0f;
    }
}

// ---------------------------------------------------------------------------
// 4) placement: drop packed (row, norm) into col's CSR slot (one STG.64)
//    -- enqueued 4th so ncu profiles it next round --
// ---------------------------------------------------------------------------
__global__ void k_place(const void* __restrict__ ei) {
    int e = blockIdx.x * blockDim.x + threadIdx.x;
    if (e >= N_EDGES) return;
    int row, col;
    if (g_is64) {
        row = (int)((const long long*)ei)[e];
        col = (int)((const long long*)ei)[(size_t)N_EDGES + e];
    } else {
        row = ((const int*)ei)[e];
        col = ((const int*)ei)[(size_t)N_EDGES + e];
    }
    float norm = g_deg[row] * g_alpha[e] * g_deg[col];
    int pos = atomicAdd(&g_wptr[col], 1);
    unsigned long long v = (unsigned)row |
                           ((unsigned long long)__float_as_uint(norm) << 32);
    g_epack[pos] = v;
}

// ---------------------------------------------------------------------------
// 5) gather + bias + LayerNorm + SiLU + residual.  One warp per node, MLP=8.
// ---------------------------------------------------------------------------
__global__ void k_gather_ln(const float* __restrict__ x, const float* __restrict__ b,
                            const float* __restrict__ gamma, const float* __restrict__ beta,
                            float* __restrict__ out) {
    __shared__ unsigned long long stage[8][40];   // 32 + 8 pad (zeros for tail)
    int wip  = threadIdx.x >> 5;
    int lane = threadIdx.x & 31;
    int node = (blockIdx.x * blockDim.x + threadIdx.x) >> 5;
    if (node >= N_NODES) return;

    if (lane < 8) stage[wip][32 + lane] = 0ull;

    int start = g_rowptr[node];
    int cnt   = g_cnt[node];

    float ax[8], ay[8];
    #pragma unroll
    for (int i = 0; i < 8; ++i) { ax[i] = 0.f; ay[i] = 0.f; }

    for (int base = 0; base < cnt; base += 32) {
        int m = cnt - base; if (m > 32) m = 32;
        unsigned long long p = 0ull;
        if (lane < m) p = g_epack[start + base + lane];
        stage[wip][lane] = p;
        __syncwarp();
        int m8 = (m + 7) & ~7;
        #pragma unroll 1
        for (int j = 0; j < m8; j += 8) {
            int   r[8]; float w[8];
            #pragma unroll
            for (int q = 0; q < 8; ++q) {
                unsigned long long pq = stage[wip][j + q];
                r[q] = (int)(unsigned)pq;
                w[q] = __uint_as_float((unsigned)(pq >> 32));
            }
            float2 v[8];
            #pragma unroll
            for (int q = 0; q < 8; ++q)
                v[q] = ((const float2*)(g_xw + (size_t)r[q] * CH))[lane];
            #pragma unroll
            for (int q = 0; q < 8; ++q) {
                ax[q] = fmaf(v[q].x, w[q], ax[q]);
                ay[q] = fmaf(v[q].y, w[q], ay[q]);
            }
        }
        __syncwarp();
    }

    float2 bb = ((const float2*)b)[lane];
    float h0 = ((ax[0] + ax[1]) + (ax[2] + ax[3])) + ((ax[4] + ax[5]) + (ax[6] + ax[7])) + bb.x;
    float h1 = ((ay[0] + ay[1]) + (ay[2] + ay[3])) + ((ay[4] + ay[5]) + (ay[6] + ay[7])) + bb.y;

    float s = h0 + h1;
    #pragma unroll
    for (int o = 16; o > 0; o >>= 1) s += __shfl_xor_sync(0xffffffffu, s, o);
    float mu = s * (1.0f / 64.0f);
    float d0 = h0 - mu, d1 = h1 - mu;
    float vs = d0 * d0 + d1 * d1;
    #pragma unroll
    for (int o = 16; o > 0; o >>= 1) vs += __shfl_xor_sync(0xffffffffu, vs, o);
    float inv = rsqrtf(vs * (1.0f / 64.0f) + 1e-5f);

    float2 gg = ((const float2*)gamma)[lane];
    float2 be = ((const float2*)beta)[lane];
    float y0 = fmaf(d0 * inv, gg.x, be.x);
    float y1 = fmaf(d1 * inv, gg.y, be.y);
    y0 = __fdividef(y0, 1.0f + __expf(-y0));
    y1 = __fdividef(y1, 1.0f + __expf(-y1));

    float2 xv = ((const float2*)(x + (size_t)node * CH))[lane];
    ((float2*)(out + (size_t)node * CH))[lane] = make_float2(y0 + xv.x, y1 + xv.y);
}

// ---------------------------------------------------------------------------
extern "C" void kernel_launch(void* const* d_in, const int* in_sizes, int n_in,
                              void* d_out, int out_size) {
    const float* x     = (const float*)d_in[0];
    const void*  ei    = d_in[1];
    const float* ea    = (const float*)d_in[2];
    const float* W     = (const float*)d_in[3];
    const float* b     = (const float*)d_in[4];
    const float* W1    = (const float*)d_in[5];
    const float* b1    = (const float*)d_in[6];
    const float* W2    = (const float*)d_in[7];
    const float* b2    = (const float*)d_in[8];
    const float* gamma = (const float*)d_in[9];
    const float* beta  = (const float*)d_in[10];
    float* out = (float*)d_out;

    static cudaStream_t s_side = nullptr;
    static cudaEvent_t  s_evFork = nullptr, s_evJoin = nullptr;
    if (!s_side) {
        cudaStreamCreateWithFlags(&s_side, cudaStreamNonBlocking);
        cudaEventCreateWithFlags(&s_evFork, cudaEventDisableTiming);
        cudaEventCreateWithFlags(&s_evJoin, cudaEventDisableTiming);
    }

    // (1) init + detect
    k_detect_init<<<(N_NODES + 255) / 256, 256>>>((const long long*)ei);
    cudaEventRecord(s_evFork, 0);

    // main chain; k_place is the 4th kernel launch -> profiled next round
    k_edge<<<(N_EDGES / 2 + 255) / 256, 256>>>(ea, ei, W1, b1, W2, b2);
    k_scan<<<NB_SCAN, 1024>>>();
    k_place<<<(N_EDGES + 255) / 256, 256>>>(ei);

    // xw on side stream (enqueued 5th; still overlaps edge/scan/place via fork event)
    cudaStreamWaitEvent(s_side, s_evFork, 0);
    k_xw<<<(N_NODES + 63) / 64, 256, 0, s_side>>>(x, W);
    cudaEventRecord(s_evJoin, s_side);

    // join: gather needs g_xw + CSR
    cudaStreamWaitEvent(0, s_evJoin, 0);
    k_gather_ln<<<(N_NODES + 7) / 8, 256>>>(x, b, gamma, beta, out);
}